// round 15
// baseline (speedup 1.0000x reference)
#include <cuda_runtime.h>
#include <cuda_fp16.h>
#include <math.h>
#include <stdint.h>

#define S_LEN 2048
#define H_DIM 4544
#define NH 71
#define HD 64
#define QKVW (H_DIM + 2*HD)   // 4672
#define KOFF (NH*HD)          // 4544
#define VOFF (KOFF + HD)      // 4608
#define HEAVY 128
#define RECENT 128

// ---------------- scratch (device globals; no allocation allowed) ------------
__device__ float g_qkv[S_LEN * QKVW];
__device__ unsigned long long g_ksum[S_LEN];
__device__ float g_cos[S_LEN * 32];
__device__ float g_sin[S_LEN * 32];
__device__ __half g_Ah[S_LEN * H_DIM];     // A (hidden / Q / attention-out), fp16
__device__ __half g_Bh[QKVW * H_DIM];      // weights transposed [N][K], fp16
__device__ __half g_Kh[S_LEN * HD];        // K fp16
__device__ __half g_Vth[HD * S_LEN];       // V transposed [d][s], fp16

// ======================= common helpers ======================================
__device__ __forceinline__ uint32_t smem_u32(const void* p) {
    uint32_t a;
    asm("{ .reg .u64 t; cvta.to.shared.u64 t, %1; cvt.u32.u64 %0, t; }" : "=r"(a) : "l"(p));
    return a;
}
__device__ __forceinline__ void cp16(uint32_t dst, const void* src, int bytes) {
    asm volatile("cp.async.cg.shared.global [%0], [%1], 16, %2;"
                 :: "r"(dst), "l"(src), "r"(bytes));
}
#define CP_COMMIT() asm volatile("cp.async.commit_group;" ::: "memory")
#define CP_WAIT0()  asm volatile("cp.async.wait_group 0;" ::: "memory")
#define CP_WAIT1()  asm volatile("cp.async.wait_group 1;" ::: "memory")
#define CP_WAIT2()  asm volatile("cp.async.wait_group 2;" ::: "memory")

#define MMA_F16(c, a, b) \
    asm volatile("mma.sync.aligned.m16n8k16.row.col.f32.f16.f16.f32 " \
        "{%0,%1,%2,%3}, {%4,%5,%6,%7}, {%8,%9}, {%0,%1,%2,%3};" \
        : "+f"((c)[0]), "+f"((c)[1]), "+f"((c)[2]), "+f"((c)[3]) \
        : "r"((a)[0]), "r"((a)[1]), "r"((a)[2]), "r"((a)[3]), \
          "r"((b)[0]), "r"((b)[1]))

__device__ __forceinline__ uint32_t pack_h2(float a, float b) {
    __half2 t = __floats2half2_rn(a, b);
    return *reinterpret_cast<uint32_t*>(&t);
}

// ---------------- convert fp32 -> fp16 (vec4) ---------------------------------
__global__ __launch_bounds__(256) void convert_f16_kernel(const float* __restrict__ X,
                                                          __half* __restrict__ Xh,
                                                          int n4)
{
    int i = blockIdx.x * 256 + threadIdx.x;
    if (i >= n4) return;
    float4 x = ((const float4*)X)[i];
    __half2 a = __floats2half2_rn(x.x, x.y);
    __half2 b = __floats2half2_rn(x.z, x.w);
    ((uint2*)Xh)[i] = make_uint2(*(uint32_t*)&a, *(uint32_t*)&b);
}

// ---------------- transpose: W[K][N] fp32 -> T[N][K] fp16 --------------------
__global__ __launch_bounds__(256) void transpose_f16_kernel(const float* __restrict__ W,
                                                            __half* __restrict__ Th,
                                                            int K, int N)
{
    __shared__ float t[32][33];
    int k0 = blockIdx.y * 32, n0 = blockIdx.x * 32;
    int c = threadIdx.x & 31, r8 = threadIdx.x >> 5;
#pragma unroll
    for (int i = 0; i < 4; i++) {
        int r = r8 + i * 8;
        t[r][c] = W[(size_t)(k0 + r) * N + n0 + c];
    }
    __syncthreads();
#pragma unroll
    for (int i = 0; i < 4; i++) {
        int r = r8 + i * 8;
        Th[(size_t)(n0 + r) * K + k0 + c] = __float2half_rn(t[c][r]);
    }
}

// ========== fp16 GEMM: C[M,N] = A @ B^T, 2 CTAs/SM for latency hiding ========
#define NSTG 3
#define MAT_BYTES 10240                 // 128 rows * 80B (40 halfs, pitch 20 words)
#define STG1_BYTES (2 * MAT_BYTES)      // A | B
#define GEMM_SMEM (NSTG * STG1_BYTES)   // 61440

__device__ __forceinline__ void gemm_prefetch(uint32_t sbase, int stg, int it,
    const __half* __restrict__ A, const __half* __restrict__ B,
    int row0, int col0, int N, int K, int tid)
{
    uint32_t st = sbase + stg * STG1_BYTES;
    const int k0 = it * 32;
#pragma unroll
    for (int t = 0; t < 4; t++) {
        int cid = t * 256 + tid;          // 1024 chunks of 16B
        int mat = cid >> 9;
        int rem = cid & 511;
        int row = rem >> 2, kc = rem & 3;
        uint32_t dst = st + mat * MAT_BYTES + row * 80 + kc * 16;
        const __half* src;
        int bytes = 16;
        if (mat == 0) {
            src = A + (size_t)(row0 + row) * K + k0 + kc * 8;
        } else {
            int n = col0 + row;
            int nc = (n < N) ? n : 0;
            bytes = (n < N) ? 16 : 0;
            src = B + (size_t)nc * K + k0 + kc * 8;
        }
        cp16(dst, src, bytes);
    }
}

__global__ __launch_bounds__(256, 2) void gemm_f16(
    const __half* __restrict__ A, const __half* __restrict__ B,
    float* __restrict__ C, int N, int K)
{
    extern __shared__ char sm[];
    const uint32_t sbase = smem_u32(sm);
    const int tid = threadIdx.x;
    const int wid = tid >> 5, lid = tid & 31;
    const int wm = wid >> 2, wn = wid & 3;
    const int g = lid >> 2, tg = lid & 3;
    const int row0 = blockIdx.y * 128, col0 = blockIdx.x * 128;
    const int niter = K / 32;

    float acc[4][4][4];
#pragma unroll
    for (int mf = 0; mf < 4; mf++)
#pragma unroll
        for (int nf = 0; nf < 4; nf++)
#pragma unroll
            for (int e = 0; e < 4; e++) acc[mf][nf][e] = 0.0f;

    gemm_prefetch(sbase, 0, 0, A, B, row0, col0, N, K, tid); CP_COMMIT();
    gemm_prefetch(sbase, 1, 1, A, B, row0, col0, N, K, tid); CP_COMMIT();

    for (int it = 0; it < niter; ++it) {
        int pf = it + 2;
        if (pf < niter)
            gemm_prefetch(sbase, pf % NSTG, pf, A, B, row0, col0, N, K, tid);
        CP_COMMIT();
        CP_WAIT2();
        __syncthreads();

        const uint32_t* sA = (const uint32_t*)(sm + (it % NSTG) * STG1_BYTES);
        const uint32_t* sB = sA + MAT_BYTES / 4;

#pragma unroll
        for (int k16 = 0; k16 < 2; ++k16) {
            const int kb = k16 * 8;
            uint32_t ah[4][4], bh[4][2];
#pragma unroll
            for (int mf = 0; mf < 4; mf++) {
                int r = wm * 64 + mf * 16 + g;
                ah[mf][0] = sA[r * 20 + kb + tg];
                ah[mf][1] = sA[(r + 8) * 20 + kb + tg];
                ah[mf][2] = sA[r * 20 + kb + tg + 4];
                ah[mf][3] = sA[(r + 8) * 20 + kb + tg + 4];
            }
#pragma unroll
            for (int nf = 0; nf < 4; nf++) {
                int n = wn * 32 + nf * 8 + g;
                bh[nf][0] = sB[n * 20 + kb + tg];
                bh[nf][1] = sB[n * 20 + kb + tg + 4];
            }
#pragma unroll
            for (int mf = 0; mf < 4; mf++)
#pragma unroll
                for (int nf = 0; nf < 4; nf++)
                    MMA_F16(acc[mf][nf], ah[mf], bh[nf]);
        }
        __syncthreads();
    }

#pragma unroll
    for (int mf = 0; mf < 4; mf++) {
        int r = row0 + wm * 64 + mf * 16 + g;
#pragma unroll
        for (int nf = 0; nf < 4; nf++) {
            int c = col0 + wn * 32 + nf * 8 + tg * 2;
            if (c < N) {
                *(float2*)&C[(size_t)r * N + c]       = make_float2(acc[mf][nf][0], acc[mf][nf][1]);
                *(float2*)&C[(size_t)(r + 8) * N + c] = make_float2(acc[mf][nf][2], acc[mf][nf][3]);
            }
        }
    }
}

// ---------------- RoPE table (fp64 arg reduction + fp32 sincos) ---------------
__global__ void rope_table_kernel()
{
    int idx = blockIdx.x * blockDim.x + threadIdx.x;
    if (idx >= S_LEN * 32) return;
    int s = idx >> 5, j = idx & 31;
    double f = exp(-(double)j / 32.0 * log(10000.0));
    double a = fmod((double)s * f, 6.283185307179586476925286766559);
    float af = (float)a;
    g_cos[idx] = cosf(af);
    g_sin[idx] = sinf(af);
}

// -------- fused rope: Q -> fp16 (scaled 1/8), K fp16; zero ksum ---------------
__global__ __launch_bounds__(256) void rope_split_kernel()
{
    int s = blockIdx.x;
    __shared__ float sc[32], ss[32];
    if (threadIdx.x < 32) {
        sc[threadIdx.x] = g_cos[s * 32 + threadIdx.x];
        ss[threadIdx.x] = g_sin[s * 32 + threadIdx.x];
    }
    if (s < 8) g_ksum[s * 256 + threadIdx.x] = 0ull;
    __syncthreads();
    const float* row = g_qkv + (size_t)s * QKVW;
    for (int e = threadIdx.x; e < 4608; e += 256) {
        int head = e >> 6, d = e & 63;
        float x  = row[head * 64 + d];
        float xp = row[head * 64 + (d ^ 32)];
        float c = sc[d & 31], sn = ss[d & 31];
        float v = (d < 32) ? (x * c - xp * sn) : (x * c + xp * sn);
        if (head < NH) {
            g_Ah[(size_t)s * H_DIM + e] = __float2half_rn(v * 0.125f);
        } else {
            g_Kh[s * HD + d] = __float2half_rn(v);
        }
    }
}

// ---------------- V transpose: g_qkv V cols -> Vt [d][s] fp16 ----------------
__global__ __launch_bounds__(256) void vtrans_kernel()
{
    __shared__ float t[32][33];
    int s0 = blockIdx.x * 32, d0 = blockIdx.y * 32;
    int c = threadIdx.x & 31, r8 = threadIdx.x >> 5;
#pragma unroll
    for (int i = 0; i < 4; i++) {
        int r = r8 + i * 8;
        t[r][c] = g_qkv[(size_t)(s0 + r) * QKVW + VOFF + d0 + c];
    }
    __syncthreads();
#pragma unroll
    for (int i = 0; i < 4; i++) {
        int r = r8 + i * 8;
        g_Vth[(size_t)(d0 + r) * S_LEN + s0 + c] = __float2half_rn(t[c][r]);
    }
}

// ====== tensor-core fused attention (single fp16 products, two-pass) =========
#define AT_PITCH 36                     // u32 per 64-half row (bank-free)
#define AT_MAT   (64 * AT_PITCH)        // 2304 u32
#define AT_MATB  (AT_MAT * 4)           // 9216 B
#define ATTN_SMEM ((11520 + 256) * 4)   // 47104 B

__device__ __forceinline__ void at_load_k(uint32_t sK, int buf, int k0, int tid)
{
    uint32_t base = sK + buf * AT_MATB;
#pragma unroll
    for (int m = 0; m < 4; m++) {
        int id = m * 128 + tid;
        int row = id >> 3, col = id & 7;
        const __half* src = g_Kh + (size_t)(k0 + row) * HD + col * 8;
        cp16(base + row * (AT_PITCH * 4) + col * 16, src, 16);
    }
}
__device__ __forceinline__ void at_load_v(uint32_t sV, int buf, int k0, int tid)
{
    uint32_t base = sV + buf * AT_MATB;
#pragma unroll
    for (int m = 0; m < 4; m++) {
        int id = m * 128 + tid;
        int row = id >> 3, col = id & 7;
        const __half* src = g_Vth + (size_t)row * S_LEN + k0 + col * 8;
        cp16(base + row * (AT_PITCH * 4) + col * 16, src, 16);
    }
}

__device__ __forceinline__ void qk_mma(float c[8][4],
    const uint32_t* __restrict__ kh_,
    const uint32_t qh[4][4], int g, int tg)
{
#pragma unroll
    for (int nt = 0; nt < 8; nt++)
        c[nt][0] = c[nt][1] = c[nt][2] = c[nt][3] = 0.0f;
#pragma unroll
    for (int kc = 0; kc < 4; kc++) {
        uint32_t bhf[8][2];
#pragma unroll
        for (int nt = 0; nt < 8; nt++) {
            int rb = (nt * 8 + g) * AT_PITCH + tg + kc * 8;
            bhf[nt][0] = kh_[rb]; bhf[nt][1] = kh_[rb + 4];
        }
#pragma unroll
        for (int nt = 0; nt < 8; nt++) MMA_F16(c[nt], qh[kc], bhf[nt]);
    }
}

__global__ __launch_bounds__(128) void attn_tc_kernel(__half* __restrict__ outH)
{
    extern __shared__ uint32_t ash[];
    uint32_t* sQh = ash;
    const uint32_t sK = smem_u32(ash + AT_MAT);
    const uint32_t sV = sK + 2 * AT_MATB;
    float* sKred = (float*)(ash + 5 * AT_MAT);   // 256 floats

    const int h = blockIdx.y, qt = blockIdx.x;
    const int q0 = qt * 64;
    const int tid = threadIdx.x;
    const int wid = tid >> 5, lane = tid & 31;
    const int g = lane >> 2, tg = lane & 3;
    const int wq = wid * 16;

    // load Q tile
#pragma unroll
    for (int m = 0; m < 4; m++) {
        int id = m * 128 + tid;
        int row = id >> 3, col = id & 7;
        const __half* src = g_Ah + (size_t)(q0 + row) * H_DIM + h * HD + col * 8;
        cp16(smem_u32(sQh + row * AT_PITCH + col * 4), src, 16);
    }
    at_load_k(sK, 0, 0, tid);
    CP_COMMIT();

    uint32_t qh[4][4];
    float rs0 = 0.f, rs1 = 0.f;
    const int qr0 = wq + g, qr1 = wq + g + 8;

    // ---------------- loop A: softmax denominators ----------------
    for (int kt = 0; kt <= qt; kt++) {
        int buf = kt & 1;
        if (kt < qt) { at_load_k(sK, buf ^ 1, (kt + 1) * 64, tid); CP_COMMIT(); CP_WAIT1(); }
        else CP_WAIT0();
        __syncthreads();
        if (kt == 0) {
            int rb = (wq + g) * AT_PITCH + tg;
#pragma unroll
            for (int kc = 0; kc < 4; kc++) {
                qh[kc][0] = sQh[rb + kc * 8];      qh[kc][1] = sQh[rb + 8 * AT_PITCH + kc * 8];
                qh[kc][2] = sQh[rb + kc * 8 + 4];  qh[kc][3] = sQh[rb + 8 * AT_PITCH + kc * 8 + 4];
            }
        }
        const uint32_t* kh_ = (const uint32_t*)(ash + AT_MAT) + buf * AT_MAT;
        float c[8][4];
        qk_mma(c, kh_, qh, g, tg);
        bool diag = (kt == qt);
#pragma unroll
        for (int nt = 0; nt < 8; nt++) {
            int kc0 = nt * 8 + 2 * tg;
            float p00, p01, p10, p11;
            if (diag) {
                p00 = (kc0     <= qr0) ? __expf(c[nt][0]) : 0.f;
                p01 = (kc0 + 1 <= qr0) ? __expf(c[nt][1]) : 0.f;
                p10 = (kc0     <= qr1) ? __expf(c[nt][2]) : 0.f;
                p11 = (kc0 + 1 <= qr1) ? __expf(c[nt][3]) : 0.f;
            } else {
                p00 = __expf(c[nt][0]); p01 = __expf(c[nt][1]);
                p10 = __expf(c[nt][2]); p11 = __expf(c[nt][3]);
            }
            rs0 += p00 + p01; rs1 += p10 + p11;
        }
        __syncthreads();
    }
    rs0 += __shfl_xor_sync(0xffffffffu, rs0, 1);
    rs0 += __shfl_xor_sync(0xffffffffu, rs0, 2);
    rs1 += __shfl_xor_sync(0xffffffffu, rs1, 1);
    rs1 += __shfl_xor_sync(0xffffffffu, rs1, 2);
    const float il0 = 1.0f / rs0, il1 = 1.0f / rs1;

    float o[8][4];
#pragma unroll
    for (int dt = 0; dt < 8; dt++)
#pragma unroll
        for (int e = 0; e < 4; e++) o[dt][e] = 0.0f;

    // ---------------- loop B: output + per-key prob sums ----------------
    at_load_k(sK, 0, 0, tid);
    at_load_v(sV, 0, 0, tid);
    CP_COMMIT();
    for (int kt = 0; kt <= qt; kt++) {
        int buf = kt & 1;
        if (kt < qt) {
            at_load_k(sK, buf ^ 1, (kt + 1) * 64, tid);
            at_load_v(sV, buf ^ 1, (kt + 1) * 64, tid);
            CP_COMMIT(); CP_WAIT1();
        } else CP_WAIT0();
        __syncthreads();
        const uint32_t* kh_ = (const uint32_t*)(ash + AT_MAT) + buf * AT_MAT;
        const uint32_t* vh_ = (const uint32_t*)(ash + AT_MAT) + (2 + buf) * AT_MAT;

        float c[8][4];
        qk_mma(c, kh_, qh, g, tg);
        bool diag = (kt == qt);
#pragma unroll
        for (int nt = 0; nt < 8; nt++) {
            int kc0 = nt * 8 + 2 * tg;
            float p00, p01, p10, p11;
            if (diag) {
                p00 = (kc0     <= qr0) ? __expf(c[nt][0]) : 0.f;
                p01 = (kc0 + 1 <= qr0) ? __expf(c[nt][1]) : 0.f;
                p10 = (kc0     <= qr1) ? __expf(c[nt][2]) : 0.f;
                p11 = (kc0 + 1 <= qr1) ? __expf(c[nt][3]) : 0.f;
            } else {
                p00 = __expf(c[nt][0]); p01 = __expf(c[nt][1]);
                p10 = __expf(c[nt][2]); p11 = __expf(c[nt][3]);
            }
            c[nt][0] = p00 * il0; c[nt][1] = p01 * il0;
            c[nt][2] = p10 * il1; c[nt][3] = p11 * il1;
        }
        // per-key prob column sums (deterministic)
#pragma unroll
        for (int nt = 0; nt < 8; nt++) {
            float cs0 = c[nt][0] + c[nt][2];
            float cs1 = c[nt][1] + c[nt][3];
            cs0 += __shfl_down_sync(0xffffffffu, cs0, 16);
            cs1 += __shfl_down_sync(0xffffffffu, cs1, 16);
            cs0 += __shfl_down_sync(0xffffffffu, cs0, 8);
            cs1 += __shfl_down_sync(0xffffffffu, cs1, 8);
            cs0 += __shfl_down_sync(0xffffffffu, cs0, 4);
            cs1 += __shfl_down_sync(0xffffffffu, cs1, 4);
            if (lane < 4) {
                sKred[wid * 64 + nt * 8 + 2 * lane]     = cs0;
                sKred[wid * 64 + nt * 8 + 2 * lane + 1] = cs1;
            }
        }
        // pack P to single fp16 A-fragments
        uint32_t pah[4][4];
#pragma unroll
        for (int kc = 0; kc < 4; kc++) {
#pragma unroll
            for (int half = 0; half < 2; half++) {
                int nt = 2 * kc + half;
                pah[kc][0 + 2 * half] = pack_h2(c[nt][0], c[nt][1]);
                pah[kc][1 + 2 * half] = pack_h2(c[nt][2], c[nt][3]);
            }
        }
        // PV: single product, product-major over 8 accumulators
#pragma unroll
        for (int kc = 0; kc < 4; kc++) {
            uint32_t vhf[8][2];
#pragma unroll
            for (int dt = 0; dt < 8; dt++) {
                int rb = (dt * 8 + g) * AT_PITCH + tg + kc * 8;
                vhf[dt][0] = vh_[rb]; vhf[dt][1] = vh_[rb + 4];
            }
#pragma unroll
            for (int dt = 0; dt < 8; dt++) MMA_F16(o[dt], pah[kc], vhf[dt]);
        }
        __syncthreads();
        if (tid < 64) {
            float c4 = sKred[tid] + sKred[64 + tid] + sKred[128 + tid] + sKred[192 + tid];
            atomicAdd(&g_ksum[kt * 64 + tid],
                      __double2ull_rn((double)c4 * 4294967296.0));
        }
    }

    // write output directly as fp16 (feeds dense GEMM)
#pragma unroll
    for (int dt = 0; dt < 8; dt++) {
        int colb = h * HD + dt * 8 + 2 * tg;
#pragma unroll
        for (int half = 0; half < 2; half++) {
            int row = q0 + wq + g + half * 8;
            *(uint32_t*)&outH[(size_t)row * H_DIM + colb] =
                pack_h2(o[dt][2 * half], o[dt][2 * half + 1]);
        }
    }
}

// ---------------- top-k + attn_mask ------------------------------------------
__device__ __forceinline__ float k2f(int i)
{
    return (float)((double)g_ksum[i] * (1.0 / 4294967296.0));
}

__global__ __launch_bounds__(1024) void topk_mask_kernel(float* __restrict__ mask_out)
{
    __shared__ float vals[2048];
    const int tid = threadIdx.x;
    for (int i = tid; i < 2048; i += 1024)
        vals[i] = (i < S_LEN - RECENT) ? k2f(i) : -3.0e38f;
    __syncthreads();

    for (int k = 2; k <= 2048; k <<= 1) {
        for (int j = k >> 1; j > 0; j >>= 1) {
            for (int t = tid; t < 2048; t += 1024) {
                int ixj = t ^ j;
                if (ixj > t) {
                    bool up = ((t & k) == 0);
                    float a = vals[t], b = vals[ixj];
                    if ((a > b) == up) { vals[t] = b; vals[ixj] = a; }
                }
            }
            __syncthreads();
        }
    }
    float thresh = vals[2048 - HEAVY];
    __syncthreads();

    for (int i = tid; i <= S_LEN; i += 1024) {
        float m;
        if (i >= S_LEN + 1 - RECENT)      m = 1.0f;
        else if (i >= S_LEN - RECENT)     m = 0.0f;
        else                              m = (k2f(i) > thresh) ? 1.0f : 0.0f;
        mask_out[i] = m;
    }
    __syncthreads();
    if (tid == 0) {
        int G = 0;
        for (int i = 0; i < S_LEN - RECENT; i++)
            if (k2f(i) > thresh) G++;
        int need = HEAVY - G;
        for (int i = 0; i < S_LEN - RECENT && need > 0; i++)
            if (k2f(i) == thresh) { mask_out[i] = 1.0f; need--; }
    }
}

// ---------------- launch ------------------------------------------------------
extern "C" void kernel_launch(void* const* d_in, const int* in_sizes, int n_in,
                              void* d_out, int out_size)
{
    (void)in_sizes; (void)n_in; (void)out_size;
    const float* hidden  = (const float*)d_in[0];
    const float* w_qkv   = (const float*)d_in[1];
    const float* w_dense = (const float*)d_in[2];
    float* out      = (float*)d_out;
    float* mask_out = out + (size_t)S_LEN * H_DIM;

    void *pq, *pah, *pbh;
    cudaGetSymbolAddress(&pq, g_qkv);
    cudaGetSymbolAddress(&pah, g_Ah);
    cudaGetSymbolAddress(&pbh, g_Bh);
    float* qkv = (float*)pq;
    __half *Ah = (__half*)pah, *Bh = (__half*)pbh;

    cudaFuncSetAttribute(gemm_f16,
                         cudaFuncAttributeMaxDynamicSharedMemorySize, GEMM_SMEM);
    cudaFuncSetAttribute(attn_tc_kernel,
                         cudaFuncAttributeMaxDynamicSharedMemorySize, ATTN_SMEM);

    const int nA4 = S_LEN * H_DIM / 4;

    // ---- GEMM 1: qkv = hidden @ w_qkv (fp16). gemm placed 4th for ncu. ----
    convert_f16_kernel<<<(nA4 + 255) / 256, 256>>>(hidden, Ah, nA4);        // 1
    dim3 gt1(QKVW / 32, H_DIM / 32);
    transpose_f16_kernel<<<gt1, 256>>>(w_qkv, Bh, H_DIM, QKVW);             // 2
    rope_table_kernel<<<(S_LEN * 32 + 1023) / 1024, 1024>>>();              // 3
    dim3 g1((QKVW + 127) / 128, S_LEN / 128);
    gemm_f16<<<g1, 256, GEMM_SMEM>>>(Ah, Bh, qkv, QKVW, H_DIM);             // 4

    // ---- rope + splits for attention (zero_ksum folded in) ----
    rope_split_kernel<<<S_LEN, 256>>>();
    dim3 gv(S_LEN / 32, HD / 32);
    vtrans_kernel<<<gv, 256>>>();

    // ---- fused tensor-core attention; writes fp16 directly ----
    dim3 ga(S_LEN / 64, NH);
    attn_tc_kernel<<<ga, 128, ATTN_SMEM>>>(Ah);

    // ---- top-k mask ----
    topk_mask_kernel<<<1, 1024>>>(mask_out);

    // ---- GEMM 2: out = attn_out @ w_dense (fp16) ----
    dim3 gt2(H_DIM / 32, H_DIM / 32);
    transpose_f16_kernel<<<gt2, 256>>>(w_dense, Bh, H_DIM, H_DIM);
    dim3 g2((H_DIM + 127) / 128, S_LEN / 128);
    gemm_f16<<<g2, 256, GEMM_SMEM>>>(Ah, Bh, out, H_DIM, H_DIM);
}

// round 16
// speedup vs baseline: 1.0280x; 1.0280x over previous
#include <cuda_runtime.h>
#include <cuda_fp16.h>
#include <math.h>
#include <stdint.h>

#define S_LEN 2048
#define H_DIM 4544
#define NH 71
#define HD 64
#define QKVW (H_DIM + 2*HD)   // 4672
#define KOFF (NH*HD)          // 4544
#define VOFF (KOFF + HD)      // 4608
#define HEAVY 128
#define RECENT 128

// ---------------- scratch (device globals; no allocation allowed) ------------
__device__ float g_qkv[S_LEN * QKVW];
__device__ unsigned long long g_ksum[S_LEN];
__device__ float g_cos[S_LEN * 32];
__device__ float g_sin[S_LEN * 32];
__device__ __half g_Ah[S_LEN * H_DIM];     // A (hidden / Q / attention-out), fp16
__device__ __half g_Bh[QKVW * H_DIM];      // weights transposed [N][K], fp16
__device__ __half g_Kh[S_LEN * HD];        // K fp16
__device__ __half g_Vth[HD * S_LEN];       // V transposed [d][s], fp16

// ======================= common helpers ======================================
__device__ __forceinline__ uint32_t smem_u32(const void* p) {
    uint32_t a;
    asm("{ .reg .u64 t; cvta.to.shared.u64 t, %1; cvt.u32.u64 %0, t; }" : "=r"(a) : "l"(p));
    return a;
}
__device__ __forceinline__ void cp16(uint32_t dst, const void* src, int bytes) {
    asm volatile("cp.async.cg.shared.global [%0], [%1], 16, %2;"
                 :: "r"(dst), "l"(src), "r"(bytes));
}
#define CP_COMMIT() asm volatile("cp.async.commit_group;" ::: "memory")
#define CP_WAIT0()  asm volatile("cp.async.wait_group 0;" ::: "memory")
#define CP_WAIT1()  asm volatile("cp.async.wait_group 1;" ::: "memory")

#define MMA_F16(c, a, b) \
    asm volatile("mma.sync.aligned.m16n8k16.row.col.f32.f16.f16.f32 " \
        "{%0,%1,%2,%3}, {%4,%5,%6,%7}, {%8,%9}, {%0,%1,%2,%3};" \
        : "+f"((c)[0]), "+f"((c)[1]), "+f"((c)[2]), "+f"((c)[3]) \
        : "r"((a)[0]), "r"((a)[1]), "r"((a)[2]), "r"((a)[3]), \
          "r"((b)[0]), "r"((b)[1]))

__device__ __forceinline__ uint32_t pack_h2(float a, float b) {
    __half2 t = __floats2half2_rn(a, b);
    return *reinterpret_cast<uint32_t*>(&t);
}

// ---------------- convert fp32 -> fp16 (vec4) ---------------------------------
__global__ __launch_bounds__(256) void convert_f16_kernel(const float* __restrict__ X,
                                                          __half* __restrict__ Xh,
                                                          int n4)
{
    int i = blockIdx.x * 256 + threadIdx.x;
    if (i >= n4) return;
    float4 x = ((const float4*)X)[i];
    __half2 a = __floats2half2_rn(x.x, x.y);
    __half2 b = __floats2half2_rn(x.z, x.w);
    ((uint2*)Xh)[i] = make_uint2(*(uint32_t*)&a, *(uint32_t*)&b);
}

// ---------------- transpose: W[K][N] fp32 -> T[N][K] fp16 --------------------
__global__ __launch_bounds__(256) void transpose_f16_kernel(const float* __restrict__ W,
                                                            __half* __restrict__ Th,
                                                            int K, int N)
{
    __shared__ float t[32][33];
    int k0 = blockIdx.y * 32, n0 = blockIdx.x * 32;
    int c = threadIdx.x & 31, r8 = threadIdx.x >> 5;
#pragma unroll
    for (int i = 0; i < 4; i++) {
        int r = r8 + i * 8;
        t[r][c] = W[(size_t)(k0 + r) * N + n0 + c];
    }
    __syncthreads();
#pragma unroll
    for (int i = 0; i < 4; i++) {
        int r = r8 + i * 8;
        Th[(size_t)(n0 + r) * K + k0 + c] = __float2half_rn(t[c][r]);
    }
}

// ========== fp16 GEMM: 4-stage ring, 2 k-iters per barrier, 2 CTAs/SM ========
#define NSTG 4
#define MAT_BYTES 10240                 // 128 rows * 80B (40 halfs, pitch 20 words)
#define STG1_BYTES (2 * MAT_BYTES)      // A | B per 32-wide k-stage
#define GEMM_SMEM (NSTG * STG1_BYTES)   // 81920

__device__ __forceinline__ void gemm_prefetch(uint32_t sbase, int stg, int it,
    const __half* __restrict__ A, const __half* __restrict__ B,
    int row0, int col0, int N, int K, int tid)
{
    uint32_t st = sbase + stg * STG1_BYTES;
    const int k0 = it * 32;
#pragma unroll
    for (int t = 0; t < 4; t++) {
        int cid = t * 256 + tid;          // 1024 chunks of 16B
        int mat = cid >> 9;
        int rem = cid & 511;
        int row = rem >> 2, kc = rem & 3;
        uint32_t dst = st + mat * MAT_BYTES + row * 80 + kc * 16;
        const __half* src;
        int bytes = 16;
        if (mat == 0) {
            src = A + (size_t)(row0 + row) * K + k0 + kc * 8;
        } else {
            int n = col0 + row;
            int nc = (n < N) ? n : 0;
            bytes = (n < N) ? 16 : 0;
            src = B + (size_t)nc * K + k0 + kc * 8;
        }
        cp16(dst, src, bytes);
    }
}

__device__ __forceinline__ void gemm_stage_mma(const char* sm, int stg,
                                               float acc[4][4][4],
                                               int wm, int wn, int g, int tg)
{
    const uint32_t* sA = (const uint32_t*)(sm + stg * STG1_BYTES);
    const uint32_t* sB = sA + MAT_BYTES / 4;
#pragma unroll
    for (int k16 = 0; k16 < 2; ++k16) {
        const int kb = k16 * 8;
        uint32_t ah[4][4], bh[4][2];
#pragma unroll
        for (int mf = 0; mf < 4; mf++) {
            int r = wm * 64 + mf * 16 + g;
            ah[mf][0] = sA[r * 20 + kb + tg];
            ah[mf][1] = sA[(r + 8) * 20 + kb + tg];
            ah[mf][2] = sA[r * 20 + kb + tg + 4];
            ah[mf][3] = sA[(r + 8) * 20 + kb + tg + 4];
        }
#pragma unroll
        for (int nf = 0; nf < 4; nf++) {
            int n = wn * 32 + nf * 8 + g;
            bh[nf][0] = sB[n * 20 + kb + tg];
            bh[nf][1] = sB[n * 20 + kb + tg + 4];
        }
#pragma unroll
        for (int mf = 0; mf < 4; mf++)
#pragma unroll
            for (int nf = 0; nf < 4; nf++)
                MMA_F16(acc[mf][nf], ah[mf], bh[nf]);
    }
}

__global__ __launch_bounds__(256, 2) void gemm_f16(
    const __half* __restrict__ A, const __half* __restrict__ B,
    float* __restrict__ C, int N, int K)
{
    extern __shared__ char sm[];
    const uint32_t sbase = smem_u32(sm);
    const int tid = threadIdx.x;
    const int wid = tid >> 5, lid = tid & 31;
    const int wm = wid >> 2, wn = wid & 3;
    const int g = lid >> 2, tg = lid & 3;
    const int row0 = blockIdx.y * 128, col0 = blockIdx.x * 128;
    const int nsuper = K / 64;            // 71 super-iters of 2 k-stages

    float acc[4][4][4];
#pragma unroll
    for (int mf = 0; mf < 4; mf++)
#pragma unroll
        for (int nf = 0; nf < 4; nf++)
#pragma unroll
            for (int e = 0; e < 4; e++) acc[mf][nf][e] = 0.0f;

    // prime two super-stages (each = 2 k-stages, one commit group per pair)
    gemm_prefetch(sbase, 0, 0, A, B, row0, col0, N, K, tid);
    gemm_prefetch(sbase, 1, 1, A, B, row0, col0, N, K, tid);
    CP_COMMIT();
    gemm_prefetch(sbase, 2, 2, A, B, row0, col0, N, K, tid);
    gemm_prefetch(sbase, 3, 3, A, B, row0, col0, N, K, tid);
    CP_COMMIT();

    for (int si = 0; si < nsuper; ++si) {
        const int ss = (si & 1) * 2;       // sub-stage base: 0 or 2
        CP_WAIT1();
        __syncthreads();
        gemm_stage_mma(sm, ss,     acc, wm, wn, g, tg);
        gemm_stage_mma(sm, ss + 1, acc, wm, wn, g, tg);
        __syncthreads();
        if (si + 2 < nsuper) {
            int it = (si + 2) * 2;
            gemm_prefetch(sbase, ss,     it,     A, B, row0, col0, N, K, tid);
            gemm_prefetch(sbase, ss + 1, it + 1, A, B, row0, col0, N, K, tid);
        }
        CP_COMMIT();
    }

#pragma unroll
    for (int mf = 0; mf < 4; mf++) {
        int r = row0 + wm * 64 + mf * 16 + g;
#pragma unroll
        for (int nf = 0; nf < 4; nf++) {
            int c = col0 + wn * 32 + nf * 8 + tg * 2;
            if (c < N) {
                *(float2*)&C[(size_t)r * N + c]       = make_float2(acc[mf][nf][0], acc[mf][nf][1]);
                *(float2*)&C[(size_t)(r + 8) * N + c] = make_float2(acc[mf][nf][2], acc[mf][nf][3]);
            }
        }
    }
}

// ---------------- RoPE table (fp64 arg reduction + fp32 sincos) ---------------
__global__ void rope_table_kernel()
{
    int idx = blockIdx.x * blockDim.x + threadIdx.x;
    if (idx >= S_LEN * 32) return;
    int s = idx >> 5, j = idx & 31;
    double f = exp(-(double)j / 32.0 * log(10000.0));
    double a = fmod((double)s * f, 6.283185307179586476925286766559);
    float af = (float)a;
    g_cos[idx] = cosf(af);
    g_sin[idx] = sinf(af);
}

// -------- fused rope: Q -> fp16 (scaled 1/8), K fp16; zero ksum ---------------
__global__ __launch_bounds__(256) void rope_split_kernel()
{
    int s = blockIdx.x;
    __shared__ float sc[32], ss[32];
    if (threadIdx.x < 32) {
        sc[threadIdx.x] = g_cos[s * 32 + threadIdx.x];
        ss[threadIdx.x] = g_sin[s * 32 + threadIdx.x];
    }
    if (s < 8) g_ksum[s * 256 + threadIdx.x] = 0ull;
    __syncthreads();
    const float* row = g_qkv + (size_t)s * QKVW;
    for (int e = threadIdx.x; e < 4608; e += 256) {
        int head = e >> 6, d = e & 63;
        float x  = row[head * 64 + d];
        float xp = row[head * 64 + (d ^ 32)];
        float c = sc[d & 31], sn = ss[d & 31];
        float v = (d < 32) ? (x * c - xp * sn) : (x * c + xp * sn);
        if (head < NH) {
            g_Ah[(size_t)s * H_DIM + e] = __float2half_rn(v * 0.125f);
        } else {
            g_Kh[s * HD + d] = __float2half_rn(v);
        }
    }
}

// ---------------- V transpose: g_qkv V cols -> Vt [d][s] fp16 ----------------
__global__ __launch_bounds__(256) void vtrans_kernel()
{
    __shared__ float t[32][33];
    int s0 = blockIdx.x * 32, d0 = blockIdx.y * 32;
    int c = threadIdx.x & 31, r8 = threadIdx.x >> 5;
#pragma unroll
    for (int i = 0; i < 4; i++) {
        int r = r8 + i * 8;
        t[r][c] = g_qkv[(size_t)(s0 + r) * QKVW + VOFF + d0 + c];
    }
    __syncthreads();
#pragma unroll
    for (int i = 0; i < 4; i++) {
        int r = r8 + i * 8;
        g_Vth[(size_t)(d0 + r) * S_LEN + s0 + c] = __float2half_rn(t[c][r]);
    }
}

// ====== tensor-core fused attention (single fp16 products, two-pass) =========
#define AT_PITCH 36                     // u32 per 64-half row (bank-free)
#define AT_MAT   (64 * AT_PITCH)        // 2304 u32
#define AT_MATB  (AT_MAT * 4)           // 9216 B
#define ATTN_SMEM ((11520 + 256) * 4)   // 47104 B

__device__ __forceinline__ void at_load_k(uint32_t sK, int buf, int k0, int tid)
{
    uint32_t base = sK + buf * AT_MATB;
#pragma unroll
    for (int m = 0; m < 4; m++) {
        int id = m * 128 + tid;
        int row = id >> 3, col = id & 7;
        const __half* src = g_Kh + (size_t)(k0 + row) * HD + col * 8;
        cp16(base + row * (AT_PITCH * 4) + col * 16, src, 16);
    }
}
__device__ __forceinline__ void at_load_v(uint32_t sV, int buf, int k0, int tid)
{
    uint32_t base = sV + buf * AT_MATB;
#pragma unroll
    for (int m = 0; m < 4; m++) {
        int id = m * 128 + tid;
        int row = id >> 3, col = id & 7;
        const __half* src = g_Vth + (size_t)row * S_LEN + k0 + col * 8;
        cp16(base + row * (AT_PITCH * 4) + col * 16, src, 16);
    }
}

__device__ __forceinline__ void qk_mma(float c[8][4],
    const uint32_t* __restrict__ kh_,
    const uint32_t qh[4][4], int g, int tg)
{
#pragma unroll
    for (int nt = 0; nt < 8; nt++)
        c[nt][0] = c[nt][1] = c[nt][2] = c[nt][3] = 0.0f;
#pragma unroll
    for (int kc = 0; kc < 4; kc++) {
        uint32_t bhf[8][2];
#pragma unroll
        for (int nt = 0; nt < 8; nt++) {
            int rb = (nt * 8 + g) * AT_PITCH + tg + kc * 8;
            bhf[nt][0] = kh_[rb]; bhf[nt][1] = kh_[rb + 4];
        }
#pragma unroll
        for (int nt = 0; nt < 8; nt++) MMA_F16(c[nt], qh[kc], bhf[nt]);
    }
}

__global__ __launch_bounds__(128) void attn_tc_kernel(__half* __restrict__ outH)
{
    extern __shared__ uint32_t ash[];
    uint32_t* sQh = ash;
    const uint32_t sK = smem_u32(ash + AT_MAT);
    const uint32_t sV = sK + 2 * AT_MATB;
    float* sKred = (float*)(ash + 5 * AT_MAT);   // 256 floats

    const int h = blockIdx.y;
    const int qt = gridDim.x - 1 - blockIdx.x;   // heavy tiles first (LPT)
    const int q0 = qt * 64;
    const int tid = threadIdx.x;
    const int wid = tid >> 5, lane = tid & 31;
    const int g = lane >> 2, tg = lane & 3;
    const int wq = wid * 16;

    // load Q tile
#pragma unroll
    for (int m = 0; m < 4; m++) {
        int id = m * 128 + tid;
        int row = id >> 3, col = id & 7;
        const __half* src = g_Ah + (size_t)(q0 + row) * H_DIM + h * HD + col * 8;
        cp16(smem_u32(sQh + row * AT_PITCH + col * 4), src, 16);
    }
    at_load_k(sK, 0, 0, tid);
    CP_COMMIT();

    uint32_t qh[4][4];
    float rs0 = 0.f, rs1 = 0.f;
    const int qr0 = wq + g, qr1 = wq + g + 8;

    // ---------------- loop A: softmax denominators ----------------
    for (int kt = 0; kt <= qt; kt++) {
        int buf = kt & 1;
        if (kt < qt) { at_load_k(sK, buf ^ 1, (kt + 1) * 64, tid); CP_COMMIT(); CP_WAIT1(); }
        else CP_WAIT0();
        __syncthreads();
        if (kt == 0) {
            int rb = (wq + g) * AT_PITCH + tg;
#pragma unroll
            for (int kc = 0; kc < 4; kc++) {
                qh[kc][0] = sQh[rb + kc * 8];      qh[kc][1] = sQh[rb + 8 * AT_PITCH + kc * 8];
                qh[kc][2] = sQh[rb + kc * 8 + 4];  qh[kc][3] = sQh[rb + 8 * AT_PITCH + kc * 8 + 4];
            }
        }
        const uint32_t* kh_ = (const uint32_t*)(ash + AT_MAT) + buf * AT_MAT;
        float c[8][4];
        qk_mma(c, kh_, qh, g, tg);
        bool diag = (kt == qt);
#pragma unroll
        for (int nt = 0; nt < 8; nt++) {
            int kc0 = nt * 8 + 2 * tg;
            float p00, p01, p10, p11;
            if (diag) {
                p00 = (kc0     <= qr0) ? __expf(c[nt][0]) : 0.f;
                p01 = (kc0 + 1 <= qr0) ? __expf(c[nt][1]) : 0.f;
                p10 = (kc0     <= qr1) ? __expf(c[nt][2]) : 0.f;
                p11 = (kc0 + 1 <= qr1) ? __expf(c[nt][3]) : 0.f;
            } else {
                p00 = __expf(c[nt][0]); p01 = __expf(c[nt][1]);
                p10 = __expf(c[nt][2]); p11 = __expf(c[nt][3]);
            }
            rs0 += p00 + p01; rs1 += p10 + p11;
        }
        __syncthreads();
    }
    rs0 += __shfl_xor_sync(0xffffffffu, rs0, 1);
    rs0 += __shfl_xor_sync(0xffffffffu, rs0, 2);
    rs1 += __shfl_xor_sync(0xffffffffu, rs1, 1);
    rs1 += __shfl_xor_sync(0xffffffffu, rs1, 2);
    const float il0 = 1.0f / rs0, il1 = 1.0f / rs1;

    float o[8][4];
#pragma unroll
    for (int dt = 0; dt < 8; dt++)
#pragma unroll
        for (int e = 0; e < 4; e++) o[dt][e] = 0.0f;

    // ---------------- loop B: output + per-key prob sums ----------------
    at_load_k(sK, 0, 0, tid);
    at_load_v(sV, 0, 0, tid);
    CP_COMMIT();
    for (int kt = 0; kt <= qt; kt++) {
        int buf = kt & 1;
        if (kt < qt) {
            at_load_k(sK, buf ^ 1, (kt + 1) * 64, tid);
            at_load_v(sV, buf ^ 1, (kt + 1) * 64, tid);
            CP_COMMIT(); CP_WAIT1();
        } else CP_WAIT0();
        __syncthreads();
        const uint32_t* kh_ = (const uint32_t*)(ash + AT_MAT) + buf * AT_MAT;
        const uint32_t* vh_ = (const uint32_t*)(ash + AT_MAT) + (2 + buf) * AT_MAT;

        float c[8][4];
        qk_mma(c, kh_, qh, g, tg);
        bool diag = (kt == qt);
#pragma unroll
        for (int nt = 0; nt < 8; nt++) {
            int kc0 = nt * 8 + 2 * tg;
            float p00, p01, p10, p11;
            if (diag) {
                p00 = (kc0     <= qr0) ? __expf(c[nt][0]) : 0.f;
                p01 = (kc0 + 1 <= qr0) ? __expf(c[nt][1]) : 0.f;
                p10 = (kc0     <= qr1) ? __expf(c[nt][2]) : 0.f;
                p11 = (kc0 + 1 <= qr1) ? __expf(c[nt][3]) : 0.f;
            } else {
                p00 = __expf(c[nt][0]); p01 = __expf(c[nt][1]);
                p10 = __expf(c[nt][2]); p11 = __expf(c[nt][3]);
            }
            c[nt][0] = p00 * il0; c[nt][1] = p01 * il0;
            c[nt][2] = p10 * il1; c[nt][3] = p11 * il1;
        }
        // per-key prob column sums (deterministic)
#pragma unroll
        for (int nt = 0; nt < 8; nt++) {
            float cs0 = c[nt][0] + c[nt][2];
            float cs1 = c[nt][1] + c[nt][3];
            cs0 += __shfl_down_sync(0xffffffffu, cs0, 16);
            cs1 += __shfl_down_sync(0xffffffffu, cs1, 16);
            cs0 += __shfl_down_sync(0xffffffffu, cs0, 8);
            cs1 += __shfl_down_sync(0xffffffffu, cs1, 8);
            cs0 += __shfl_down_sync(0xffffffffu, cs0, 4);
            cs1 += __shfl_down_sync(0xffffffffu, cs1, 4);
            if (lane < 4) {
                sKred[wid * 64 + nt * 8 + 2 * lane]     = cs0;
                sKred[wid * 64 + nt * 8 + 2 * lane + 1] = cs1;
            }
        }
        // pack P to single fp16 A-fragments
        uint32_t pah[4][4];
#pragma unroll
        for (int kc = 0; kc < 4; kc++) {
#pragma unroll
            for (int half = 0; half < 2; half++) {
                int nt = 2 * kc + half;
                pah[kc][0 + 2 * half] = pack_h2(c[nt][0], c[nt][1]);
                pah[kc][1 + 2 * half] = pack_h2(c[nt][2], c[nt][3]);
            }
        }
        // PV: single product, product-major over 8 accumulators
#pragma unroll
        for (int kc = 0; kc < 4; kc++) {
            uint32_t vhf[8][2];
#pragma unroll
            for (int dt = 0; dt < 8; dt++) {
                int rb = (dt * 8 + g) * AT_PITCH + tg + kc * 8;
                vhf[dt][0] = vh_[rb]; vhf[dt][1] = vh_[rb + 4];
            }
#pragma unroll
            for (int dt = 0; dt < 8; dt++) MMA_F16(o[dt], pah[kc], vhf[dt]);
        }
        __syncthreads();
        if (tid < 64) {
            float c4 = sKred[tid] + sKred[64 + tid] + sKred[128 + tid] + sKred[192 + tid];
            atomicAdd(&g_ksum[kt * 64 + tid],
                      __double2ull_rn((double)c4 * 4294967296.0));
        }
    }

    // write output directly as fp16 (feeds dense GEMM)
#pragma unroll
    for (int dt = 0; dt < 8; dt++) {
        int colb = h * HD + dt * 8 + 2 * tg;
#pragma unroll
        for (int half = 0; half < 2; half++) {
            int row = q0 + wq + g + half * 8;
            *(uint32_t*)&outH[(size_t)row * H_DIM + colb] =
                pack_h2(o[dt][2 * half], o[dt][2 * half + 1]);
        }
    }
}

// ---------------- top-k + attn_mask ------------------------------------------
__device__ __forceinline__ float k2f(int i)
{
    return (float)((double)g_ksum[i] * (1.0 / 4294967296.0));
}

__global__ __launch_bounds__(1024) void topk_mask_kernel(float* __restrict__ mask_out)
{
    __shared__ float vals[2048];
    const int tid = threadIdx.x;
    for (int i = tid; i < 2048; i += 1024)
        vals[i] = (i < S_LEN - RECENT) ? k2f(i) : -3.0e38f;
    __syncthreads();

    for (int k = 2; k <= 2048; k <<= 1) {
        for (int j = k >> 1; j > 0; j >>= 1) {
            for (int t = tid; t < 2048; t += 1024) {
                int ixj = t ^ j;
                if (ixj > t) {
                    bool up = ((t & k) == 0);
                    float a = vals[t], b = vals[ixj];
                    if ((a > b) == up) { vals[t] = b; vals[ixj] = a; }
                }
            }
            __syncthreads();
        }
    }
    float thresh = vals[2048 - HEAVY];
    __syncthreads();

    for (int i = tid; i <= S_LEN; i += 1024) {
        float m;
        if (i >= S_LEN + 1 - RECENT)      m = 1.0f;
        else if (i >= S_LEN - RECENT)     m = 0.0f;
        else                              m = (k2f(i) > thresh) ? 1.0f : 0.0f;
        mask_out[i] = m;
    }
    __syncthreads();
    if (tid == 0) {
        int G = 0;
        for (int i = 0; i < S_LEN - RECENT; i++)
            if (k2f(i) > thresh) G++;
        int need = HEAVY - G;
        for (int i = 0; i < S_LEN - RECENT && need > 0; i++)
            if (k2f(i) == thresh) { mask_out[i] = 1.0f; need--; }
    }
}

// ---------------- launch ------------------------------------------------------
extern "C" void kernel_launch(void* const* d_in, const int* in_sizes, int n_in,
                              void* d_out, int out_size)
{
    (void)in_sizes; (void)n_in; (void)out_size;
    const float* hidden  = (const float*)d_in[0];
    const float* w_qkv   = (const float*)d_in[1];
    const float* w_dense = (const float*)d_in[2];
    float* out      = (float*)d_out;
    float* mask_out = out + (size_t)S_LEN * H_DIM;

    void *pq, *pah, *pbh;
    cudaGetSymbolAddress(&pq, g_qkv);
    cudaGetSymbolAddress(&pah, g_Ah);
    cudaGetSymbolAddress(&pbh, g_Bh);
    float* qkv = (float*)pq;
    __half *Ah = (__half*)pah, *Bh = (__half*)pbh;

    cudaFuncSetAttribute(gemm_f16,
                         cudaFuncAttributeMaxDynamicSharedMemorySize, GEMM_SMEM);
    cudaFuncSetAttribute(attn_tc_kernel,
                         cudaFuncAttributeMaxDynamicSharedMemorySize, ATTN_SMEM);

    const int nA4 = S_LEN * H_DIM / 4;

    // ---- GEMM 1: qkv = hidden @ w_qkv (fp16). gemm placed 4th for ncu. ----
    convert_f16_kernel<<<(nA4 + 255) / 256, 256>>>(hidden, Ah, nA4);        // 1
    dim3 gt1(QKVW / 32, H_DIM / 32);
    transpose_f16_kernel<<<gt1, 256>>>(w_qkv, Bh, H_DIM, QKVW);             // 2
    rope_table_kernel<<<(S_LEN * 32 + 1023) / 1024, 1024>>>();              // 3
    dim3 g1((QKVW + 127) / 128, S_LEN / 128);
    gemm_f16<<<g1, 256, GEMM_SMEM>>>(Ah, Bh, qkv, QKVW, H_DIM);             // 4

    // ---- rope + splits for attention (zero_ksum folded in) ----
    rope_split_kernel<<<S_LEN, 256>>>();
    dim3 gv(S_LEN / 32, HD / 32);
    vtrans_kernel<<<gv, 256>>>();

    // ---- fused tensor-core attention; writes fp16 directly ----
    dim3 ga(S_LEN / 64, NH);
    attn_tc_kernel<<<ga, 128, ATTN_SMEM>>>(Ah);

    // ---- top-k mask ----
    topk_mask_kernel<<<1, 1024>>>(mask_out);

    // ---- GEMM 2: out = attn_out @ w_dense (fp16) ----
    dim3 gt2(H_DIM / 32, H_DIM / 32);
    transpose_f16_kernel<<<gt2, 256>>>(w_dense, Bh, H_DIM, H_DIM);
    dim3 g2((H_DIM + 127) / 128, S_LEN / 128);
    gemm_f16<<<g2, 256, GEMM_SMEM>>>(Ah, Bh, out, H_DIM, H_DIM);
}